// round 8
// baseline (speedup 1.0000x reference)
#include <cuda_runtime.h>
#include <stdint.h>

#define Mv 128
#define Nv 256
#define Cv 22
#define TILE (Cv*Cv)                  // 484 floats per (i,j) tile
#define JC 8                          // j per chunk
#define NJH (Nv/2)                    // 128 j per main CTA
#define NCH (NJH/JC)                  // 16 chunks
#define NSTAGES 3
#define STAGE_FLOATS (JC*TILE)        // 3872 floats
#define STAGE_BYTES  (STAGE_FLOATS*4) // 15488 B
#define CHALF 11

__device__ unsigned g_dselp[(Nv/4) * Mv];       // [j4][m], 4 packed classes/word
__device__ float    g_hi[2 * Nv * 256 * CHALF]; // [h][i][t][cc]
__device__ float    g_part[Nv * Mv];            // [i][m]

__device__ __forceinline__ unsigned smem_u32(const void* p) {
    return (unsigned)__cvta_generic_to_shared(p);
}

// ---------------------------------------------------------------------------
__global__ void prep_kernel(const int* __restrict__ variant) {
    int tid = blockIdx.x * blockDim.x + threadIdx.x;    // 8192 = 128m x 64 j4
    int m  = tid >> 6;
    int j4 = tid & 63;
    int4 v = ((const int4*)variant)[m * 64 + j4];       // coalesced
    unsigned w = (unsigned)v.x | ((unsigned)v.y << 8) |
                 ((unsigned)v.z << 16) | ((unsigned)v.w << 24);
    g_dselp[j4 * Mv + m] = w;
}

// ---------------------------------------------------------------------------
// main: 512 CTAs = (i, j-half). No inter-CTA sync -> safe at any residency.
// ---------------------------------------------------------------------------
__global__ __launch_bounds__(256, 4) void main_kernel(
    const float* __restrict__ eij,
    const float* __restrict__ mask_vec)
{
    __shared__ __align__(128) float sE[NSTAGES][STAGE_FLOATS];   // 46464 B
    __shared__ __align__(8) unsigned long long mbar[NSTAGES];
    __shared__ float smask[32];

    const int bx = blockIdx.x;
    const int i  = bx >> 1;
    const int h  = bx & 1;
    const int t  = threadIdx.x;
    const int m  = t & (Mv - 1);
    const int c0 = (t >> 7) * CHALF;

    if (t < Cv) smask[t] = mask_vec[t];
    if (t == 0) {
        #pragma unroll
        for (int s = 0; s < NSTAGES; ++s)
            asm volatile("mbarrier.init.shared.b64 [%0], 1;"
                         :: "r"(smem_u32(&mbar[s])));
    }
    __syncthreads();

    const char* gsrc = (const char*)(eij + ((size_t)i * Nv + (size_t)h * NJH) * TILE);

    if (t == 0) {
        #pragma unroll
        for (int k = 0; k < 2; ++k) {
            unsigned bar = smem_u32(&mbar[k]);
            asm volatile("mbarrier.arrive.expect_tx.shared::cta.b64 _, [%0], %1;"
                         :: "r"(bar), "r"((unsigned)STAGE_BYTES));
            asm volatile("cp.async.bulk.shared::cta.global.mbarrier::complete_tx::bytes "
                         "[%0], [%1], %2, [%3];"
                         :: "r"(smem_u32(&sE[k][0])),
                            "l"(gsrc + (size_t)k * STAGE_BYTES),
                            "r"((unsigned)STAGE_BYTES), "r"(bar) : "memory");
        }
    }

    float acc[CHALF];
    #pragma unroll
    for (int cc = 0; cc < CHALF; ++cc) acc[cc] = 0.0f;

    const int w4base = h * (NJH / 4);   // packed-word offset for this half

    for (int k = 0; k < NCH; ++k) {
        const int s = k % NSTAGES;
        const unsigned ph = (unsigned)(k / NSTAGES) & 1u;

        unsigned w0 = g_dselp[(w4base + k * 2 + 0) * Mv + m];
        unsigned w1 = g_dselp[(w4base + k * 2 + 1) * Mv + m];

        {   // wait for chunk k (r7-proven)
            unsigned bar = smem_u32(&mbar[s]);
            unsigned done;
            asm volatile("{\n .reg .pred p;\n"
                         " mbarrier.try_wait.parity.acquire.cta.shared::cta.b64 p, [%1], %2;\n"
                         " selp.b32 %0, 1, 0, p;\n}"
                         : "=r"(done) : "r"(bar), "r"(ph) : "memory");
            while (!done) {
                asm volatile("{\n .reg .pred p;\n"
                             " mbarrier.try_wait.parity.acquire.cta.shared::cta.b64 p, [%1], %2, 0x989680;\n"
                             " selp.b32 %0, 1, 0, p;\n}"
                             : "=r"(done) : "r"(bar), "r"(ph) : "memory");
            }
        }

        int d8[8];
        #pragma unroll
        for (int b = 0; b < 4; ++b) {
            d8[b]     = (w0 >> (8 * b)) & 0xFF;
            d8[4 + b] = (w1 >> (8 * b)) & 0xFF;
        }
        float s8[8];
        #pragma unroll
        for (int jj = 0; jj < 8; ++jj) s8[jj] = smask[d8[jj]];

        const float* buf = sE[s];
        #pragma unroll
        for (int jj = 0; jj < JC; ++jj) {
            const float* row = buf + jj * TILE + c0 * Cv + d8[jj];
            const float sc = s8[jj];
            #pragma unroll
            for (int cc = 0; cc < CHALF; ++cc)
                acc[cc] = fmaf(sc, row[cc * Cv], acc[cc]);   // conflict-free LDS
        }

        __syncthreads();
        if (t == 0 && k + 2 < NCH) {
            const int kn = k + 2;
            unsigned bar = smem_u32(&mbar[kn % NSTAGES]);
            asm volatile("mbarrier.arrive.expect_tx.shared::cta.b64 _, [%0], %1;"
                         :: "r"(bar), "r"((unsigned)STAGE_BYTES));
            asm volatile("cp.async.bulk.shared::cta.global.mbarrier::complete_tx::bytes "
                         "[%0], [%1], %2, [%3];"
                         :: "r"(smem_u32(&sE[kn % NSTAGES][0])),
                            "l"(gsrc + (size_t)kn * STAGE_BYTES),
                            "r"((unsigned)STAGE_BYTES), "r"(bar) : "memory");
        }
    }

    // partial hi out (warp writes 1408 contiguous bytes)
    float* gp = g_hi + ((size_t)(h * Nv + i) * 256 + t) * CHALF;
    #pragma unroll
    for (int cc = 0; cc < CHALF; ++cc) gp[cc] = acc[cc];
}

// ---------------------------------------------------------------------------
// combine: 256 CTAs (one per i) — r7 epilogue verbatim
// ---------------------------------------------------------------------------
__global__ __launch_bounds__(256) void combine_kernel(
    const int*   __restrict__ variant,
    const float* __restrict__ vmask,
    const float* __restrict__ ei,
    const float* __restrict__ sigma,
    float* __restrict__ motifs,      // [Mv,Nv,Cv]
    float* __restrict__ logits)      // [Mv,Nv]
{
    __shared__ float sei[Cv];
    __shared__ float slog[Mv];

    const int i  = blockIdx.x;
    const int t  = threadIdx.x;
    const int m  = t & (Mv - 1);
    const int c0 = (t >> 7) * CHALF;

    if (t < Cv) sei[t] = ei[i * Cv + t];
    __syncthreads();

    const float* p0 = g_hi + ((size_t)(0 * Nv + i) * 256 + t) * CHALF;
    const float* p1 = g_hi + ((size_t)(1 * Nv + i) * 256 + t) * CHALF;
    const int vmi = variant[m * Nv + i];
    const bool own = (vmi >= c0) && (vmi < c0 + CHALF);
    float* mout = motifs + ((size_t)m * Nv + i) * Cv;
    float myl = 0.0f;
    #pragma unroll
    for (int cc = 0; cc < CHALF; ++cc) {
        const int c = c0 + cc;
        const float v = p0[cc] + p1[cc] + sei[c];
        mout[c] = v;
        if (c == vmi) myl = v;
    }
    if (own) slog[m] = myl;
    __syncthreads();

    if (t < Mv) {
        const float lm = slog[t];
        logits[t * Nv + i] = lm;
        const float w = vmask[t * Nv + i] * vmask[i];
        g_part[i * Mv + t] = (lm - slog[0]) * w * sigma[0];
    }
}

// ---------------------------------------------------------------------------
// reduce: 128 CTAs — vlog[m] = sum_i g_part[i][m]
// ---------------------------------------------------------------------------
__global__ __launch_bounds__(256) void reduce_kernel(float* __restrict__ vlog) {
    __shared__ float red[256];
    const int mb = blockIdx.x;
    const int t  = threadIdx.x;
    red[t] = g_part[t * Mv + mb];
    __syncthreads();
    #pragma unroll
    for (int st = 128; st > 0; st >>= 1) {
        if (t < st) red[t] += red[t + st];
        __syncthreads();
    }
    if (t == 0) vlog[mb] = red[0];
}

// ---------------------------------------------------------------------------
extern "C" void kernel_launch(void* const* d_in, const int* in_sizes, int n_in,
                              void* d_out, int out_size) {
    int idx_eij = 2, idx_ei = 3, idx_mask = 4, idx_sigma = 5;
    int big1 = 0, big2 = 1;
    {
        int b1 = -1, b2 = -1;
        for (int q = 0; q < n_in; ++q) {
            int s = in_sizes[q];
            if (s == Nv * Nv * Cv * Cv)      idx_eij = q;
            else if (s == Nv * Cv)           idx_ei = q;
            else if (s == Cv)                idx_mask = q;
            else if (s == 1)                 idx_sigma = q;
            else if (s == Mv * Nv) { if (b1 < 0) b1 = q; else b2 = q; }
        }
        if (b1 >= 0) big1 = b1;
        if (b2 >= 0) big2 = b2;
    }

    const int*   variant = (const int*)d_in[big1];
    const float* vmask   = (const float*)d_in[big2];
    const float* eij     = (const float*)d_in[idx_eij];
    const float* ei      = (const float*)d_in[idx_ei];
    const float* maskv   = (const float*)d_in[idx_mask];
    const float* sigma   = (const float*)d_in[idx_sigma];

    float* out    = (float*)d_out;
    float* motifs = out;                               // [128,256,22]
    float* logits = out + (size_t)Mv * Nv * Cv;        // [128,256]
    float* vlog   = logits + (size_t)Mv * Nv;          // [128,1]

    prep_kernel<<<32, 256>>>(variant);
    main_kernel<<<2 * Nv, 256>>>(eij, maskv);
    combine_kernel<<<Nv, 256>>>(variant, vmask, ei, sigma, motifs, logits);
    reduce_kernel<<<Mv, 256>>>(vlog);
}

// round 9
// speedup vs baseline: 1.0925x; 1.0925x over previous
#include <cuda_runtime.h>
#include <stdint.h>

#define Mv 128
#define Nv 256
#define Cv 22
#define TILE (Cv*Cv)                  // 484 floats per (i,j) tile
#define JC 8                          // j per chunk (4 per team)
#define NCHUNK (Nv/JC)                // 32
#define NSTAGES 3
#define STAGE_FLOATS (JC*TILE)        // 3872 floats
#define STAGE_BYTES  (STAGE_FLOATS*4) // 15488 B
#define CHALF 11
#define NB 256

__device__ unsigned g_dselp[(Nv/4) * Mv];        // [j4][m] packed classes
__device__ float    g_acc[Nv * 256 * CHALF];     // team-B accs [i][tb][cc]

__device__ __forceinline__ unsigned smem_u32(const void* p) {
    return (unsigned)__cvta_generic_to_shared(p);
}

// ---------------------------------------------------------------------------
// prep: pack variant -> [j4][m] words; zero vlog (atomic target in d_out)
// ---------------------------------------------------------------------------
__global__ void prep_kernel(const int* __restrict__ variant,
                            float* __restrict__ vlog) {
    int tid = blockIdx.x * blockDim.x + threadIdx.x;    // 8192 = 128m x 64 j4
    int m  = tid >> 6;
    int j4 = tid & 63;
    int4 v = ((const int4*)variant)[m * 64 + j4];       // coalesced
    unsigned w = (unsigned)v.x | ((unsigned)v.y << 8) |
                 ((unsigned)v.z << 16) | ((unsigned)v.w << 24);
    g_dselp[j4 * Mv + m] = w;
    if (tid < Mv) vlog[tid] = 0.0f;
}

// ---------------------------------------------------------------------------
// fused: 256 CTAs x 512 threads. r7 pipeline skeleton; two teams split jj.
// No inter-CTA sync anywhere -> deadlock impossible at any residency.
// ---------------------------------------------------------------------------
__global__ __launch_bounds__(512, 2) void fused_kernel(
    const int*   __restrict__ variant,
    const float* __restrict__ vmask,
    const float* __restrict__ eij,
    const float* __restrict__ ei,
    const float* __restrict__ mask_vec,
    const float* __restrict__ sigma,
    float* __restrict__ motifs,      // [Mv,Nv,Cv]
    float* __restrict__ logits,      // [Mv,Nv]
    float* __restrict__ vlog)        // [Mv]
{
    __shared__ __align__(128) float sE[NSTAGES][STAGE_FLOATS];   // 46464 B
    __shared__ __align__(8) unsigned long long mbar[NSTAGES];
    __shared__ float smask[32];
    __shared__ float sei[Cv];
    __shared__ float slog[Mv];

    const int i    = blockIdx.x;
    const int t    = threadIdx.x;           // 0..511
    const int team = t >> 8;                // 0: jj 0-3, 1: jj 4-7
    const int tb   = t & 255;               // (m, c-half) id within team
    const int m    = tb & (Mv - 1);
    const int c0   = ((tb >> 7) & 1) * CHALF;

    if (t < Cv) { smask[t] = mask_vec[t]; sei[t] = ei[i * Cv + t]; }
    if (t == 0) {
        #pragma unroll
        for (int s = 0; s < NSTAGES; ++s)
            asm volatile("mbarrier.init.shared.b64 [%0], 1;"
                         :: "r"(smem_u32(&mbar[s])));
    }
    __syncthreads();

    const char* gsrc = (const char*)(eij + (size_t)i * (Nv * TILE));

    // prime 2 chunks (r7-proven protocol, thread 0 only)
    if (t == 0) {
        #pragma unroll
        for (int k = 0; k < 2; ++k) {
            unsigned bar = smem_u32(&mbar[k]);
            asm volatile("mbarrier.arrive.expect_tx.shared::cta.b64 _, [%0], %1;"
                         :: "r"(bar), "r"((unsigned)STAGE_BYTES));
            asm volatile("cp.async.bulk.shared::cta.global.mbarrier::complete_tx::bytes "
                         "[%0], [%1], %2, [%3];"
                         :: "r"(smem_u32(&sE[k][0])),
                            "l"(gsrc + (size_t)k * STAGE_BYTES),
                            "r"((unsigned)STAGE_BYTES), "r"(bar) : "memory");
        }
    }

    float acc[CHALF];
    #pragma unroll
    for (int cc = 0; cc < CHALF; ++cc) acc[cc] = 0.0f;

    const int jj0 = team * 4;   // this team's first jj within a chunk

    for (int k = 0; k < NCHUNK; ++k) {
        const int s = k % NSTAGES;
        const unsigned ph = (unsigned)(k / NSTAGES) & 1u;

        // this team's 4 class ids: ONE coalesced word per thread
        unsigned w0 = g_dselp[(k * 2 + team) * Mv + m];

        {   // wait for chunk k (r7-proven)
            unsigned bar = smem_u32(&mbar[s]);
            unsigned done;
            asm volatile("{\n .reg .pred p;\n"
                         " mbarrier.try_wait.parity.acquire.cta.shared::cta.b64 p, [%1], %2;\n"
                         " selp.b32 %0, 1, 0, p;\n}"
                         : "=r"(done) : "r"(bar), "r"(ph) : "memory");
            while (!done) {
                asm volatile("{\n .reg .pred p;\n"
                             " mbarrier.try_wait.parity.acquire.cta.shared::cta.b64 p, [%1], %2, 0x989680;\n"
                             " selp.b32 %0, 1, 0, p;\n}"
                             : "=r"(done) : "r"(bar), "r"(ph) : "memory");
            }
        }

        int d4[4];
        #pragma unroll
        for (int b = 0; b < 4; ++b) d4[b] = (w0 >> (8 * b)) & 0xFF;
        float s4[4];
        #pragma unroll
        for (int b = 0; b < 4; ++b) s4[b] = smask[d4[b]];

        const float* buf = sE[s];
        #pragma unroll
        for (int jl = 0; jl < 4; ++jl) {
            const float* row = buf + (jj0 + jl) * TILE + c0 * Cv + d4[jl];
            const float sc = s4[jl];
            #pragma unroll
            for (int cc = 0; cc < CHALF; ++cc)
                acc[cc] = fmaf(sc, row[cc * Cv], acc[cc]);   // conflict-free LDS
        }

        __syncthreads();   // all 512 done with chunk k -> stage (k-1)%3 reusable
        if (t == 0 && k + 2 < NCHUNK) {
            const int kn = k + 2;
            unsigned bar = smem_u32(&mbar[kn % NSTAGES]);
            asm volatile("mbarrier.arrive.expect_tx.shared::cta.b64 _, [%0], %1;"
                         :: "r"(bar), "r"((unsigned)STAGE_BYTES));
            asm volatile("cp.async.bulk.shared::cta.global.mbarrier::complete_tx::bytes "
                         "[%0], [%1], %2, [%3];"
                         :: "r"(smem_u32(&sE[kn % NSTAGES][0])),
                            "l"(gsrc + (size_t)kn * STAGE_BYTES),
                            "r"((unsigned)STAGE_BYTES), "r"(bar) : "memory");
        }
    }

    // ---- merge team-B accs into team-A via global scratch (intra-CTA) ----
    if (team == 1) {
        float* gp = g_acc + ((size_t)i * 256 + tb) * CHALF;
        #pragma unroll
        for (int cc = 0; cc < CHALF; ++cc) gp[cc] = acc[cc];
    }
    __syncthreads();

    if (team == 0) {
        const float* gp = g_acc + ((size_t)i * 256 + tb) * CHALF;
        const int vmi = variant[m * Nv + i];
        const bool own = (vmi >= c0) && (vmi < c0 + CHALF);
        float* mout = motifs + ((size_t)m * Nv + i) * Cv;
        float myl = 0.0f;
        #pragma unroll
        for (int cc = 0; cc < CHALF; ++cc) {
            const int c = c0 + cc;
            const float v = acc[cc] + gp[cc] + sei[c];
            mout[c] = v;
            if (c == vmi) myl = v;
        }
        if (own) slog[m] = myl;
    }
    __syncthreads();

    if (t < Mv) {
        const float lm = slog[t];
        logits[t * Nv + i] = lm;
        const float w = vmask[t * Nv + i] * vmask[i];
        atomicAdd(&vlog[t], (lm - slog[0]) * w * sigma[0]);
    }
}

// ---------------------------------------------------------------------------
extern "C" void kernel_launch(void* const* d_in, const int* in_sizes, int n_in,
                              void* d_out, int out_size) {
    int idx_eij = 2, idx_ei = 3, idx_mask = 4, idx_sigma = 5;
    int big1 = 0, big2 = 1;
    {
        int b1 = -1, b2 = -1;
        for (int q = 0; q < n_in; ++q) {
            int s = in_sizes[q];
            if (s == Nv * Nv * Cv * Cv)      idx_eij = q;
            else if (s == Nv * Cv)           idx_ei = q;
            else if (s == Cv)                idx_mask = q;
            else if (s == 1)                 idx_sigma = q;
            else if (s == Mv * Nv) { if (b1 < 0) b1 = q; else b2 = q; }
        }
        if (b1 >= 0) big1 = b1;
        if (b2 >= 0) big2 = b2;
    }

    const int*   variant = (const int*)d_in[big1];
    const float* vmask   = (const float*)d_in[big2];
    const float* eij     = (const float*)d_in[idx_eij];
    const float* ei      = (const float*)d_in[idx_ei];
    const float* maskv   = (const float*)d_in[idx_mask];
    const float* sigma   = (const float*)d_in[idx_sigma];

    float* out    = (float*)d_out;
    float* motifs = out;                               // [128,256,22]
    float* logits = out + (size_t)Mv * Nv * Cv;        // [128,256]
    float* vlog   = logits + (size_t)Mv * Nv;          // [128,1]

    prep_kernel<<<32, 256>>>(variant, vlog);
    fused_kernel<<<NB, 512>>>(variant, vmask, eij, ei, maskv, sigma,
                              motifs, logits, vlog);
}

// round 10
// speedup vs baseline: 1.2387x; 1.1338x over previous
#include <cuda_runtime.h>
#include <stdint.h>

#define Mv 128
#define Nv 256
#define Cv 22
#define TILE (Cv*Cv)                  // 484 floats per (i,j) tile
#define JC 16                         // j per chunk
#define NCHUNK (Nv/JC)                // 16 chunks
#define NST 2                         // double buffer
#define STAGE_FLOATS (JC*TILE)        // 7744 floats
#define STAGE_BYTES  (STAGE_FLOATS*4) // 30976 B
#define DSMEM (NST*STAGE_BYTES)       // 61952 B dynamic
#define CHALF 11
#define NB 256

__device__ unsigned g_dselp[(Nv/4) * Mv];   // [j4][m], 4 packed classes/word

__device__ __forceinline__ unsigned smem_u32(const void* p) {
    return (unsigned)__cvta_generic_to_shared(p);
}

__device__ __forceinline__ void wait_parity(unsigned bar, unsigned ph) {
    unsigned done;
    asm volatile("{\n .reg .pred p;\n"
                 " mbarrier.try_wait.parity.acquire.cta.shared::cta.b64 p, [%1], %2;\n"
                 " selp.b32 %0, 1, 0, p;\n}"
                 : "=r"(done) : "r"(bar), "r"(ph) : "memory");
    while (!done) {
        asm volatile("{\n .reg .pred p;\n"
                     " mbarrier.try_wait.parity.acquire.cta.shared::cta.b64 p, [%1], %2, 0x989680;\n"
                     " selp.b32 %0, 1, 0, p;\n}"
                     : "=r"(done) : "r"(bar), "r"(ph) : "memory");
    }
}

// ---------------------------------------------------------------------------
// prep: pack variant -> [j4][m] words; zero vlog (atomicAdd target)
// ---------------------------------------------------------------------------
__global__ void prep_kernel(const int* __restrict__ variant,
                            float* __restrict__ vlog) {
    int tid = blockIdx.x * blockDim.x + threadIdx.x;    // 8192 = 128m x 64 j4
    int m  = tid >> 6;
    int j4 = tid & 63;
    int4 v = ((const int4*)variant)[m * 64 + j4];       // coalesced
    unsigned w = (unsigned)v.x | ((unsigned)v.y << 8) |
                 ((unsigned)v.z << 16) | ((unsigned)v.w << 24);
    g_dselp[j4 * Mv + m] = w;
    if (tid < Mv) vlog[tid] = 0.0f;
}

// ---------------------------------------------------------------------------
// fused: 256 CTAs x 256 threads, JC=16 double-buffered TMA pipeline.
// No inter-CTA dependency anywhere -> correct at ANY residency (no deadlock).
// ---------------------------------------------------------------------------
__global__ __launch_bounds__(256, 2) void fused_kernel(
    const int*   __restrict__ variant,
    const float* __restrict__ vmask,
    const float* __restrict__ eij,
    const float* __restrict__ ei,
    const float* __restrict__ mask_vec,
    const float* __restrict__ sigma,
    float* __restrict__ motifs,      // [Mv,Nv,Cv]
    float* __restrict__ logits,      // [Mv,Nv]
    float* __restrict__ vlog)        // [Mv]
{
    extern __shared__ __align__(128) float sE[];        // [NST][STAGE_FLOATS]
    __shared__ __align__(8) unsigned long long mbar[NST];
    __shared__ float smask[32];
    __shared__ float sei[Cv];
    __shared__ float slog[Mv];

    const int i  = blockIdx.x;
    const int t  = threadIdx.x;
    const int m  = t & (Mv - 1);
    const int c0 = (t >> 7) * CHALF;

    if (t < Cv) { smask[t] = mask_vec[t]; sei[t] = ei[i * Cv + t]; }
    if (t == 0) {
        #pragma unroll
        for (int s = 0; s < NST; ++s)
            asm volatile("mbarrier.init.shared.b64 [%0], 1;"
                         :: "r"(smem_u32(&mbar[s])));
    }
    __syncthreads();

    const char* gsrc = (const char*)(eij + (size_t)i * (Nv * TILE));

    // prime both stages
    if (t == 0) {
        #pragma unroll
        for (int k = 0; k < 2; ++k) {
            unsigned bar = smem_u32(&mbar[k]);
            asm volatile("mbarrier.arrive.expect_tx.shared::cta.b64 _, [%0], %1;"
                         :: "r"(bar), "r"((unsigned)STAGE_BYTES));
            asm volatile("cp.async.bulk.shared::cta.global.mbarrier::complete_tx::bytes "
                         "[%0], [%1], %2, [%3];"
                         :: "r"(smem_u32(sE) + k * STAGE_BYTES),
                            "l"(gsrc + (size_t)k * STAGE_BYTES),
                            "r"((unsigned)STAGE_BYTES), "r"(bar) : "memory");
        }
    }

    float acc[CHALF];
    #pragma unroll
    for (int cc = 0; cc < CHALF; ++cc) acc[cc] = 0.0f;

    for (int k = 0; k < NCHUNK; ++k) {
        const int s = k & 1;
        const unsigned ph = (unsigned)(k >> 1) & 1u;

        // 4 coalesced words = 16 class ids, loaded before the wait
        unsigned w4[4];
        #pragma unroll
        for (int q = 0; q < 4; ++q)
            w4[q] = g_dselp[(k * 4 + q) * Mv + m];

        wait_parity(smem_u32(&mbar[s]), ph);

        const float* buf = sE + s * STAGE_FLOATS;
        #pragma unroll
        for (int half = 0; half < 2; ++half) {          // 8 j per half-pass
            const unsigned wa = w4[half * 2], wb = w4[half * 2 + 1];
            int d8[8];
            #pragma unroll
            for (int b = 0; b < 4; ++b) {
                d8[b]     = (wa >> (8 * b)) & 0xFF;
                d8[4 + b] = (wb >> (8 * b)) & 0xFF;
            }
            float s8[8];
            #pragma unroll
            for (int jj = 0; jj < 8; ++jj) s8[jj] = smask[d8[jj]];

            #pragma unroll
            for (int jl = 0; jl < 8; ++jl) {
                const float* row = buf + (half * 8 + jl) * TILE + c0 * Cv + d8[jl];
                const float sc = s8[jl];
                #pragma unroll
                for (int cc = 0; cc < CHALF; ++cc)
                    acc[cc] = fmaf(sc, row[cc * Cv], acc[cc]);  // conflict-free LDS
            }
        }

        __syncthreads();   // all done with chunk k -> stage s reusable
        if (t == 0 && k + 2 < NCHUNK) {
            const int kn = k + 2;                       // same stage s, next phase
            unsigned bar = smem_u32(&mbar[s]);
            asm volatile("mbarrier.arrive.expect_tx.shared::cta.b64 _, [%0], %1;"
                         :: "r"(bar), "r"((unsigned)STAGE_BYTES));
            asm volatile("cp.async.bulk.shared::cta.global.mbarrier::complete_tx::bytes "
                         "[%0], [%1], %2, [%3];"
                         :: "r"(smem_u32(sE) + s * STAGE_BYTES),
                            "l"(gsrc + (size_t)kn * STAGE_BYTES),
                            "r"((unsigned)STAGE_BYTES), "r"(bar) : "memory");
        }
    }

    // ---- epilogue: motifs, logits, atomic pooled delta (r9-proven) ----
    const int vmi = variant[m * Nv + i];
    float* mout = motifs + ((size_t)m * Nv + i) * Cv;
    float myl = 0.0f;
    const bool own = (vmi >= c0) && (vmi < c0 + CHALF);
    #pragma unroll
    for (int cc = 0; cc < CHALF; ++cc) {
        const int c = c0 + cc;
        const float v = acc[cc] + sei[c];
        mout[c] = v;
        if (c == vmi) myl = v;
    }
    if (own) slog[m] = myl;
    __syncthreads();

    if (t < Mv) {
        const float lm = slog[t];
        logits[t * Nv + i] = lm;
        const float w = vmask[t * Nv + i] * vmask[i];
        atomicAdd(&vlog[t], (lm - slog[0]) * w * sigma[0]);
    }
}

// ---------------------------------------------------------------------------
// Set the >48KB dynamic-smem opt-in at binary load time — NEVER inside
// kernel_launch (capture-time attribute calls correlate 3/3 with the
// container failures in rounds 4-6).
// ---------------------------------------------------------------------------
static struct _AttrInit {
    _AttrInit() {
        cudaFuncSetAttribute(fused_kernel,
                             cudaFuncAttributeMaxDynamicSharedMemorySize, DSMEM);
    }
} _attr_init;

// ---------------------------------------------------------------------------
extern "C" void kernel_launch(void* const* d_in, const int* in_sizes, int n_in,
                              void* d_out, int out_size) {
    int idx_eij = 2, idx_ei = 3, idx_mask = 4, idx_sigma = 5;
    int big1 = 0, big2 = 1;
    {
        int b1 = -1, b2 = -1;
        for (int q = 0; q < n_in; ++q) {
            int s = in_sizes[q];
            if (s == Nv * Nv * Cv * Cv)      idx_eij = q;
            else if (s == Nv * Cv)           idx_ei = q;
            else if (s == Cv)                idx_mask = q;
            else if (s == 1)                 idx_sigma = q;
            else if (s == Mv * Nv) { if (b1 < 0) b1 = q; else b2 = q; }
        }
        if (b1 >= 0) big1 = b1;
        if (b2 >= 0) big2 = b2;
    }

    const int*   variant = (const int*)d_in[big1];
    const float* vmask   = (const float*)d_in[big2];
    const float* eij     = (const float*)d_in[idx_eij];
    const float* ei      = (const float*)d_in[idx_ei];
    const float* maskv   = (const float*)d_in[idx_mask];
    const float* sigma   = (const float*)d_in[idx_sigma];

    float* out    = (float*)d_out;
    float* motifs = out;                               // [128,256,22]
    float* logits = out + (size_t)Mv * Nv * Cv;        // [128,256]
    float* vlog   = logits + (size_t)Mv * Nv;          // [128,1]

    prep_kernel<<<32, 256>>>(variant, vlog);
    fused_kernel<<<NB, 256, DSMEM>>>(variant, vmask, eij, ei, maskv, sigma,
                                     motifs, logits, vlog);
}